// round 13
// baseline (speedup 1.0000x reference)
#include <cuda_runtime.h>
#include <cuda_bf16.h>
#include <cstdint>

#define B_ 32
#define L_ 1024
#define D_ 64

typedef __nv_bfloat16 bf16;

// energy bf16 hi/lo splits, [b][j][e] (e contiguous, 128B rows)
__device__ __align__(16) bf16 g_egy_hi[B_ * L_ * D_];
__device__ __align__(16) bf16 g_egy_lo[B_ * L_ * D_];

// ---------------------------------------------------------------------------
// helpers
// ---------------------------------------------------------------------------
__device__ __forceinline__ uint32_t smem_u32(const void* p) {
    uint32_t a;
    asm("{ .reg .u64 t; cvta.to.shared.u64 t, %1; cvt.u32.u64 %0, t; }"
        : "=r"(a) : "l"(p));
    return a;
}
__device__ __forceinline__ void cp16(void* dst_smem, const void* src) {
    uint32_t s = smem_u32(dst_smem);
    asm volatile("cp.async.cg.shared.global [%0], [%1], 16;" :: "r"(s), "l"(src));
}
__device__ __forceinline__ void cp_commit() { asm volatile("cp.async.commit_group;"); }
template <int N>
__device__ __forceinline__ void cp_wait() {
    asm volatile("cp.async.wait_group %0;" :: "n"(N));
}
__device__ __forceinline__ void ldsm_x4(uint32_t addr, uint32_t r[4]) {
    asm volatile("ldmatrix.sync.aligned.m8n8.x4.shared.b16 {%0,%1,%2,%3}, [%4];"
                 : "=r"(r[0]), "=r"(r[1]), "=r"(r[2]), "=r"(r[3]) : "r"(addr));
}
__device__ __forceinline__ void mma16816(float c[4], const uint32_t a[4],
                                         const uint32_t b0, const uint32_t b1) {
    asm volatile(
        "mma.sync.aligned.m16n8k16.row.col.f32.bf16.bf16.f32 "
        "{%0,%1,%2,%3}, {%4,%5,%6,%7}, {%8,%9}, {%0,%1,%2,%3};"
        : "+f"(c[0]), "+f"(c[1]), "+f"(c[2]), "+f"(c[3])
        : "r"(a[0]), "r"(a[1]), "r"(a[2]), "r"(a[3]), "r"(b0), "r"(b1));
}
__device__ __forceinline__ uint32_t swz(uint32_t o) { return o ^ ((o >> 3) & 0x70); }

__device__ __forceinline__ void split2(float a, float b, uint32_t& h, uint32_t& l) {
    bf16 ha = __float2bfloat16_rn(a), hb = __float2bfloat16_rn(b);
    bf16 la = __float2bfloat16_rn(a - __bfloat162float(ha));
    bf16 lb = __float2bfloat16_rn(b - __bfloat162float(hb));
    __nv_bfloat162 hh = __halves2bfloat162(ha, hb);
    __nv_bfloat162 ll = __halves2bfloat162(la, lb);
    h = *reinterpret_cast<uint32_t*>(&hh);
    l = *reinterpret_cast<uint32_t*>(&ll);
}

// ---------------------------------------------------------------------------
// Kernel 1: energy[b][j][e] = sum_d enc[b][j][d]*W[e][d] + bias[e] -> bf16 hi/lo
// grid (8 j-blocks, 32 b), 256 threads
// ---------------------------------------------------------------------------
__global__ __launch_bounds__(256) void energy_kernel(
    const float* __restrict__ enc, const float* __restrict__ W,
    const float* __restrict__ bias) {
    __shared__ float Wt[D_][D_];     // [d][e]
    __shared__ float encs[D_][128];  // [d][j]; reused as enT[e][j]
    const int b = blockIdx.y, jb = blockIdx.x;
    const int tid = threadIdx.x;

    const float4* W4 = reinterpret_cast<const float4*>(W);
#pragma unroll
    for (int i = 0; i < 4; i++) {
        int f = tid + i * 256;
        int e = f >> 4, dq = f & 15;
        float4 w = W4[f];
        Wt[dq * 4 + 0][e] = w.x; Wt[dq * 4 + 1][e] = w.y;
        Wt[dq * 4 + 2][e] = w.z; Wt[dq * 4 + 3][e] = w.w;
    }
    const float4* enc4 =
        reinterpret_cast<const float4*>(enc + ((size_t)b * L_ + (size_t)jb * 128) * D_);
#pragma unroll
    for (int i = 0; i < 8; i++) {
        int f = tid + i * 256;
        int j = f >> 4, dq = f & 15;
        float4 v = enc4[f];
        encs[dq * 4 + 0][j] = v.x; encs[dq * 4 + 1][j] = v.y;
        encs[dq * 4 + 2][j] = v.z; encs[dq * 4 + 3][j] = v.w;
    }
    __syncthreads();

    const int w = tid >> 5, lane = tid & 31;
    const int e0 = w * 8;
    float acc[8][4];
#pragma unroll
    for (int e = 0; e < 8; e++)
#pragma unroll
        for (int q = 0; q < 4; q++) acc[e][q] = 0.f;
#pragma unroll 4
    for (int d = 0; d < D_; d++) {
        float4 ev = *reinterpret_cast<const float4*>(&encs[d][lane * 4]);
        float4 wa = *reinterpret_cast<const float4*>(&Wt[d][e0]);
        float4 wb = *reinterpret_cast<const float4*>(&Wt[d][e0 + 4]);
        float wv[8] = {wa.x, wa.y, wa.z, wa.w, wb.x, wb.y, wb.z, wb.w};
#pragma unroll
        for (int e = 0; e < 8; e++) {
            acc[e][0] = fmaf(wv[e], ev.x, acc[e][0]);
            acc[e][1] = fmaf(wv[e], ev.y, acc[e][1]);
            acc[e][2] = fmaf(wv[e], ev.z, acc[e][2]);
            acc[e][3] = fmaf(wv[e], ev.w, acc[e][3]);
        }
    }
    __syncthreads();   // done reading encs as [d][j]
#pragma unroll
    for (int e = 0; e < 8; e++) {
        float bb = bias[e0 + e];
        float4 o = make_float4(acc[e][0] + bb, acc[e][1] + bb,
                               acc[e][2] + bb, acc[e][3] + bb);
        *reinterpret_cast<float4*>(&encs[e0 + e][lane * 4]) = o;  // enT[e][j]
    }
    __syncthreads();

    // emit bf16 hi/lo, layout [j][e]
    const int j = tid >> 1, eh = (tid & 1) * 32;
    const size_t row = (size_t)b * L_ + jb * 128 + j;
    uint32_t hp[16], lp[16];
#pragma unroll
    for (int k = 0; k < 16; k++) {
        float v0 = encs[eh + 2 * k][j];
        float v1 = encs[eh + 2 * k + 1][j];
        split2(v0, v1, hp[k], lp[k]);
    }
    uint4* dh = reinterpret_cast<uint4*>(g_egy_hi + row * D_ + eh);
    uint4* dl = reinterpret_cast<uint4*>(g_egy_lo + row * D_ + eh);
#pragma unroll
    for (int q = 0; q < 4; q++) {
        dh[q] = make_uint4(hp[4 * q], hp[4 * q + 1], hp[4 * q + 2], hp[4 * q + 3]);
        dl[q] = make_uint4(lp[4 * q], lp[4 * q + 1], lp[4 * q + 2], lp[4 * q + 3]);
    }
}

// ---------------------------------------------------------------------------
// Kernel 2: WARP-AUTONOMOUS scores kernel, 3-stage private rings.
// grid (32 tb, 32 b), 512 threads (16 warps). CTA: 32 t x 1024 j.
// warp w: mb = w&1 (m16 block), ng = w>>1 owns j-band [ng*128,(ng+1)*128),
// processed as 8 sub-slabs of 16 j-rows.
// Each warp streams B through a PRIVATE 3-stage ring (3 x 4KB: hi 2KB + lo
// 2KB per stage) with its own cp.async groups; wait_group(2) + __syncwarp().
// Effective pipeline depth 2 sub-slabs -> ~2x latency-hiding budget vs R12.
// A fragments register-resident. Per-sub-slab fused exp epilogue.
// ---------------------------------------------------------------------------
#define A_HI 0
#define A_LO 4096
#define BB   8192
#define STAGE 4096
#define NSTG 3
#define WSTRIDE (NSTG * STAGE)   // 12 KB per warp
#define SUMS_OFF (BB + 16 * WSTRIDE)
#define SMEM_TOTAL (SUMS_OFF + 8 * 32 * 4)

__global__ __launch_bounds__(512, 1) void scores_mma_kernel(
    const float* __restrict__ enc, float* __restrict__ out) {
    extern __shared__ char smem[];
    const uint32_t sb = smem_u32(smem);
    float* sums = reinterpret_cast<float*>(smem + SUMS_OFF);  // [8 ng][32 rows]

    const int tid = threadIdx.x, w = tid >> 5, lane = tid & 31;
    const int mb = w & 1, ng = w >> 1;
    const int b = blockIdx.y, tb = blockIdx.x, t0 = tb * 32;
    const int g = lane >> 2, qc = lane & 3;

    // ---- A: load enc fp32 tile (32 x 64), split to bf16 hi/lo smem ----
    {
        const float4* src =
            reinterpret_cast<const float4*>(enc + ((size_t)b * L_ + t0) * D_);
        float4 v = src[tid];                 // 512 float4 = whole tile
        int row = tid >> 4, c = tid & 15;
        uint2 h, l;
        split2(v.x, v.y, h.x, l.x);
        split2(v.z, v.w, h.y, l.y);
        uint32_t off = swz(row * 128 + c * 8);
        *reinterpret_cast<uint2*>(smem + A_HI + off) = h;
        *reinterpret_cast<uint2*>(smem + A_LO + off) = l;
    }

    // ---- per-warp private B sub-slab loader (3-stage ring) ----
    char* const wptr = smem + BB + w * WSTRIDE;
    const char* bhb = reinterpret_cast<const char*>(g_egy_hi + (size_t)b * L_ * D_);
    const char* blb = reinterpret_cast<const char*>(g_egy_lo + (size_t)b * L_ * D_);
    const int jband = ng * 128;
    auto load_ss = [&](int ss) {
        char* dst = wptr + (ss % NSTG) * STAGE;
        const size_t j0 = (size_t)(jband + ss * 16);
        // 16 rows x 8 chunks x 2 splits = 256 chunks, 8 per lane
#pragma unroll
        for (int i = 0; i < 8; i++) {
            int id = lane + i * 32;
            int split = id >> 7, rem = id & 127, row = rem >> 3, cc = rem & 7;
            cp16(dst + split * 2048 + swz(row * 128 + cc * 16),
                 (split ? blb : bhb) + (j0 + row) * 128 + cc * 16);
        }
        cp_commit();
    };
    load_ss(0);
    load_ss(1);
    load_ss(2);

    __syncthreads();   // A split visible to all warps (only CTA sync pre-loop)

    // ---- prologue: A fragments for this warp's m16 block into registers ----
    uint32_t af[4][2][4];      // [ks][split][4]
    {
        const uint32_t a_lrow = (uint32_t)(mb * 16 + (lane & 15));
        const uint32_t a_kb = (uint32_t)((lane >> 4) * 8);
#pragma unroll
        for (int ks = 0; ks < 4; ks++) {
            uint32_t aoff = swz(a_lrow * 128 + (a_kb + ks * 16) * 2);
            ldsm_x4(sb + A_HI + aoff, af[ks][0]);
            ldsm_x4(sb + A_LO + aoff, af[ks][1]);
        }
    }

    // hoisted B-fragment smem offsets (ss-invariant)
    uint32_t boffs[4];
    {
        const uint32_t b_rowoff = (uint32_t)(((lane >> 4) & 1) * 8 + (lane & 7));
        const uint32_t b_kb = (uint32_t)(((lane >> 3) & 1) * 8);
#pragma unroll
        for (int ks = 0; ks < 4; ks++)
            boffs[ks] = swz(b_rowoff * 128 + (b_kb + ks * 16) * 2);
    }

    float acc[8][2][4];        // [sub-slab][nt2][4]; exp'd in place per ss
    const uint32_t wbase = sb + BB + w * WSTRIDE;

    const int r0 = t0 + mb * 16 + g;     // this thread's two t-rows
    const int r1 = r0 + 8;
    float s0 = 0.f, s1 = 0.f;            // running row sums

#pragma unroll
    for (int ss = 0; ss < 8; ss++) {
#pragma unroll
        for (int nt = 0; nt < 2; nt++)
#pragma unroll
            for (int q = 0; q < 4; q++) acc[ss][nt][q] = 0.f;

        cp_wait<2>();          // own groups: sub-slab ss resident
        __syncwarp();          // make all lanes' cp.async data visible in-warp

        const uint32_t bb2 = wbase + (ss % NSTG) * STAGE;
        float* P0 = acc[ss][0];
        float* P1 = acc[ss][1];
#pragma unroll
        for (int ks = 0; ks < 4; ks++) {
            uint32_t bh[4], bl[4];
            ldsm_x4(bb2 + boffs[ks], bh);
            ldsm_x4(bb2 + 2048 + boffs[ks], bl);
            const uint32_t* ah = af[ks][0];
            const uint32_t* al = af[ks][1];
            mma16816(P0, ah, bh[0], bh[1]);
            mma16816(P1, ah, bh[2], bh[3]);
            mma16816(P0, al, bh[0], bh[1]);
            mma16816(P1, al, bh[2], bh[3]);
            mma16816(P0, ah, bl[0], bl[1]);
            mma16816(P1, ah, bl[2], bl[3]);
        }
        __syncwarp();          // all lanes done reading this stage
        if (ss + 3 < 8) load_ss(ss + 3);
        else cp_commit();      // keep group accounting uniform

        // ---- per-sub-slab epilogue: diag zero + exp + running sums ----
        // (overlaps in-flight cp.async; no max-sub: |s| < ~45, fp32-safe)
#pragma unroll
        for (int nt = 0; nt < 2; nt++) {
            const int j = jband + ss * 16 + nt * 8 + qc * 2;
            float* a = acc[ss][nt];
            float v0 = (j == r0) ? 0.f : a[0];
            float v1 = (j + 1 == r0) ? 0.f : a[1];
            float v2 = (j == r1) ? 0.f : a[2];
            float v3 = (j + 1 == r1) ? 0.f : a[3];
            v0 = __expf(v0); v1 = __expf(v1); v2 = __expf(v2); v3 = __expf(v3);
            a[0] = v0; a[1] = v1; a[2] = v2; a[3] = v3;
            s0 += v0 + v1; s1 += v2 + v3;
        }
    }

    // ---- cross-thread / cross-warp row-sum reduction ----
#pragma unroll
    for (int o = 1; o < 4; o <<= 1) {
        s0 += __shfl_xor_sync(0xffffffffu, s0, o);
        s1 += __shfl_xor_sync(0xffffffffu, s1, o);
    }
    if (qc == 0) {
        sums[ng * 32 + mb * 16 + g] = s0;
        sums[ng * 32 + mb * 16 + g + 8] = s1;
    }
    __syncthreads();

    const int lr0 = mb * 16 + g, lr1 = lr0 + 8;
    float tot0 = 0.f, tot1 = 0.f;
#pragma unroll
    for (int q = 0; q < 8; q++) {
        tot0 += sums[q * 32 + lr0];
        tot1 += sums[q * 32 + lr1];
    }
    const float rinv0 = 1.0f / tot0, rinv1 = 1.0f / tot1;

    // ---- normalize + store out[t][b][j] ----
    float* out0 = out + (((size_t)r0 * B_ + b) << 10);
    float* out1 = out + (((size_t)r1 * B_ + b) << 10);
#pragma unroll
    for (int ss = 0; ss < 8; ss++)
#pragma unroll
        for (int nt = 0; nt < 2; nt++) {
            const int j = jband + ss * 16 + nt * 8 + qc * 2;
            float* a = acc[ss][nt];
            *reinterpret_cast<float2*>(out0 + j) =
                make_float2(a[0] * rinv0, a[1] * rinv0);
            *reinterpret_cast<float2*>(out1 + j) =
                make_float2(a[2] * rinv1, a[3] * rinv1);
        }
}

// ---------------------------------------------------------------------------
extern "C" void kernel_launch(void* const* d_in, const int* in_sizes, int n_in,
                              void* d_out, int out_size) {
    (void)in_sizes; (void)n_in; (void)out_size;
    const float* enc  = (const float*)d_in[0];
    const float* W    = (const float*)d_in[1];
    const float* bias = (const float*)d_in[2];
    float* out = (float*)d_out;

    static int configured = 0;
    if (!configured) {
        cudaFuncSetAttribute(scores_mma_kernel,
                             cudaFuncAttributeMaxDynamicSharedMemorySize, SMEM_TOTAL);
        configured = 1;
    }

    energy_kernel<<<dim3(8, 32), 256>>>(enc, W, bias);
    scores_mma_kernel<<<dim3(32, 32), 512, SMEM_TOTAL>>>(enc, out);
}